// round 11
// baseline (speedup 1.0000x reference)
#include <cuda_runtime.h>
#include <cstdint>

#define ROW_LEN 2048
#define NTHREADS 256
#define VPT 8
#define K_TOP 64
#define NBINS 128            // tail bins over x in [1.15625, 5.09375); bin0 = catch-all below
#define FSCALE 32.0f
#define FBIAS  -36.0f
#define FULLMASK 0xffffffffu

__global__ __launch_bounds__(NTHREADS, 8)   // cap regs at 32 -> 8 CTAs/SM
void topk_softmax_kernel(const float* __restrict__ in, float* __restrict__ out) {
    const int tid  = threadIdx.x;
    const int lane = tid & 31;
    const int wid  = tid >> 5;
    const size_t rbase = (size_t)blockIdx.x * ROW_LEN;

    const float4* rp4 = reinterpret_cast<const float4*>(in + rbase);
    float4*       op4 = reinterpret_cast<float4*>(out + rbase);

    __shared__ int   hist[NBINS];
    __shared__ float cand[ROW_LEN];      // crossing-bin candidates (worst-case safe)
    __shared__ int   s_bin, s_kc, s_cnt;
    __shared__ float s_vk, s_sum;

    // ---- 1. Issue loads (streaming; single-use data); zero scratch in flight ----
    float4 a = __ldcs(rp4 + tid);
    float4 b = __ldcs(rp4 + tid + NTHREADS);
    if (tid < NBINS) hist[tid] = 0;
    if (tid == 0) { s_cnt = 0; s_sum = 0.0f; }

    float v[VPT];
    v[0] = a.x; v[1] = a.y; v[2] = a.z; v[3] = a.w;
    v[4] = b.x; v[5] = b.y; v[6] = b.z; v[7] = b.w;
    __syncthreads();                                          // B1

    // ---- 2. Conditional tail histogram: only ~12% of elements take an atomic ----
    #pragma unroll
    for (int i = 0; i < VPT; i++) {
        float f = fmaf(v[i], FSCALE, FBIAS);
        if (f >= 1.0f)
            atomicAdd(&hist[min((int)f, NBINS - 1)], 1);
    }
    __syncthreads();                                          // B2

    // ---- 3. Warp 0 alone: suffix scan of 128 bins (4/lane), locate crossing ----
    if (wid == 0) {
        int4 h4 = reinterpret_cast<int4*>(hist)[lane];   // bins 4L .. 4L+3
        int hh0 = h4.x, hh1 = h4.y, hh2 = h4.z, hh3 = h4.w;
        const int lsum = hh0 + hh1 + hh2 + hh3;
        int s = lsum;                               // suffix incl. own bins
        #pragma unroll
        for (int o = 1; o < 32; o <<= 1) {
            int t = __shfl_down_sync(FULLMASK, s, o);
            if (lane + o < 32) s += t;
        }
        const int total = __shfl_sync(FULLMASK, s, 0);  // count of all histed elems
        int suf = s - lsum;                         // count in bins strictly above mine
        if (suf < K_TOP && s >= K_TOP) {            // unique lane owns the crossing
            int t3 = suf + hh3, t2 = t3 + hh2, t1 = t2 + hh1, t0 = t1 + hh0;
            if      (t3 >= K_TOP) { s_bin = lane * 4 + 3; s_kc = K_TOP - suf; }
            else if (t2 >= K_TOP) { s_bin = lane * 4 + 2; s_kc = K_TOP - t3;  }
            else if (t1 >= K_TOP) { s_bin = lane * 4 + 1; s_kc = K_TOP - t2;  }
            else                  { s_bin = lane * 4;     s_kc = K_TOP - t1;  }
        }
        if (lane == 0 && total < K_TOP) {           // catch-all: threshold below range
            s_bin = 0;
            s_kc  = K_TOP - total;
        }
    }
    __syncthreads();                                          // B3

    // ---- 4. Compact the crossing bin's elements ----
    const int bstar = s_bin;
    const int kc    = s_kc;
    const float flo = (bstar == 0)         ? -__int_as_float(0x7f800000) : (float)bstar;
    const float fhi = (bstar == NBINS - 1) ?  __int_as_float(0x7f800000) : (float)(bstar + 1);
    #pragma unroll
    for (int i = 0; i < VPT; i++) {
        float f = fmaf(v[i], FSCALE, FBIAS);        // identical FMA as binning
        if (f >= flo && f < fhi) {
            int idx = atomicAdd(&s_cnt, 1);
            cand[idx] = v[i];
        }
    }
    __syncthreads();                                          // B4

    // ---- 5. Warp 0: exact kc-th largest among candidates (tie-robust) ----
    if (wid == 0) {
        const int c = s_cnt;                        // typically ~4-5
        int   remaining = kc;
        float bound = __int_as_float(0x7f800000);   // +inf
        float vk;
        for (;;) {
            float m = -__int_as_float(0x7f800000);
            for (int i = lane; i < c; i += 32) {
                float x = cand[i];
                if (x < bound) m = fmaxf(m, x);
            }
            #pragma unroll
            for (int o = 16; o; o >>= 1) m = fmaxf(m, __shfl_xor_sync(FULLMASK, m, o));
            int cnt = 0;
            for (int i = lane; i < c; i += 32) cnt += (cand[i] == m);
            #pragma unroll
            for (int o = 16; o; o >>= 1) cnt += __shfl_xor_sync(FULLMASK, cnt, o);
            if (cnt >= remaining) { vk = m; break; }
            remaining -= cnt;
            bound = m;
        }
        if (lane == 0) s_vk = vk;
    }
    __syncthreads();                                          // B5

    // ---- 6. Masked exp + sum (offset by vk; softmax is shift-invariant) ----
    const float vk = s_vk;
    float sum = 0.0f;
    #pragma unroll
    for (int i = 0; i < VPT; i++) {
        float ev = (v[i] >= vk) ? __expf(v[i] - vk) : 0.0f;
        v[i] = ev;
        sum += ev;
    }
    #pragma unroll
    for (int o = 16; o; o >>= 1) sum += __shfl_xor_sync(FULLMASK, sum, o);
    if (lane == 0) atomicAdd(&s_sum, sum);
    __syncthreads();                                          // B6

    const float inv = __fdividef(1.0f, s_sum);

    // ---- 7. Store (coalesced float4, streaming) ----
    float4 o1 = make_float4(v[0] * inv, v[1] * inv, v[2] * inv, v[3] * inv);
    float4 o2 = make_float4(v[4] * inv, v[5] * inv, v[6] * inv, v[7] * inv);
    __stcs(op4 + tid,            o1);
    __stcs(op4 + tid + NTHREADS, o2);
}

extern "C" void kernel_launch(void* const* d_in, const int* in_sizes, int n_in,
                              void* d_out, int out_size) {
    const float* in  = (const float*)d_in[0];
    float*       out = (float*)d_out;
    const int nrows = in_sizes[0] / ROW_LEN;   // 2*16*2048 = 65536
    topk_softmax_kernel<<<nrows, NTHREADS>>>(in, out);
}

// round 12
// speedup vs baseline: 1.1392x; 1.1392x over previous
#include <cuda_runtime.h>
#include <cstdint>

#define ROW_LEN 2048
#define NTHREADS 256
#define NWARP 8
#define VPT 8
#define K_TOP 64
#define NBINS 512            // bins 1..511 cover x in [1.0, 5.0); bin 0 = derived catch-all
#define FSCALE 128.0f
#define FBIAS  -127.0f
#define FULLMASK 0xffffffffu

__global__ __launch_bounds__(NTHREADS, 8)   // cap regs at 32 -> 8 CTAs/SM
void topk_softmax_kernel(const float* __restrict__ in, float* __restrict__ out) {
    const int tid  = threadIdx.x;
    const int lane = tid & 31;
    const int wid  = tid >> 5;
    const size_t rbase = (size_t)blockIdx.x * ROW_LEN;

    const float4* rp4 = reinterpret_cast<const float4*>(in + rbase);
    float4*       op4 = reinterpret_cast<float4*>(out + rbase);

    __shared__ int   hist[NBINS];
    __shared__ float cand[ROW_LEN];      // crossing-bin candidates (worst-case safe)
    __shared__ int   s_wsum[NWARP];
    __shared__ int   s_bin, s_kc, s_cnt;
    __shared__ float s_vk, s_sum;

    // ---- 1. Issue loads; zero histogram while they're in flight ----
    float4 a = rp4[tid];
    float4 b = rp4[tid + NTHREADS];
    reinterpret_cast<int2*>(hist)[tid] = make_int2(0, 0);
    if (tid == 0) { s_cnt = 0; s_sum = 0.0f; }

    float v[VPT];
    v[0] = a.x; v[1] = a.y; v[2] = a.z; v[3] = a.w;
    v[4] = b.x; v[5] = b.y; v[6] = b.z; v[7] = b.w;
    __syncthreads();                                          // B1

    // ---- 2. Conditional tail histogram: only x >= 1.0 (~16%) take an atomic ----
    #pragma unroll
    for (int i = 0; i < VPT; i++) {
        float f = fmaf(v[i], FSCALE, FBIAS);
        if (f >= 1.0f)
            atomicAdd(&hist[min((int)f, NBINS - 1)], 1);
    }
    __syncthreads();                                          // B2

    // ---- 3. Distributed suffix scan; thread t owns bins (2t, 2t+1) ----
    const int2 h = reinterpret_cast<int2*>(hist)[tid];
    const int lsum = h.x + h.y;
    int s = lsum;                                 // warp suffix incl. self
    #pragma unroll
    for (int o = 1; o < 32; o <<= 1) {
        int t = __shfl_down_sync(FULLMASK, s, o);
        if (lane + o < 32) s += t;
    }
    if (lane == 0) s_wsum[wid] = s;
    __syncthreads();                                          // B3

    int T = s - lsum;                             // count in bins strictly above my pair
    #pragma unroll
    for (int w = 1; w < NWARP; w++)
        if (w > wid) T += s_wsum[w];

    if (T < K_TOP && T + lsum >= K_TOP) {         // unique thread owns the crossing
        const int nsuf = T + h.y;                 // bin 2t+1 is the higher bin
        if (nsuf >= K_TOP) {
            s_bin = tid * 2 + 1;
            s_kc  = K_TOP - T;
        } else {
            s_bin = tid * 2;
            s_kc  = K_TOP - nsuf;
        }
    }
    if (tid == 0) {                               // catch-all: threshold below range
        const int total = T + lsum;               // thread 0's suffix = all histed elems
        if (total < K_TOP) {
            s_bin = 0;
            s_kc  = K_TOP - total;
        }
    }
    __syncthreads();                                          // B4

    // ---- 4. Compact the crossing bin's elements ----
    const int bstar = s_bin;
    const int kc    = s_kc;
    const float flo = (bstar == 0)         ? -__int_as_float(0x7f800000) : (float)bstar;
    const float fhi = (bstar == NBINS - 1) ?  __int_as_float(0x7f800000) : (float)(bstar + 1);
    #pragma unroll
    for (int i = 0; i < VPT; i++) {
        float f = fmaf(v[i], FSCALE, FBIAS);      // identical FMA as binning
        if (f >= flo && f < fhi) {
            int idx = atomicAdd(&s_cnt, 1);
            cand[idx] = v[i];
        }
    }
    __syncthreads();                                          // B5

    // ---- 5. Warp 0 only: exact kc-th largest among candidates (tie-robust) ----
    if (wid == 0) {
        const int c = s_cnt;                      // usually ~1-2
        int   remaining = kc;
        float bound = __int_as_float(0x7f800000); // +inf
        float vk;
        for (;;) {
            float m = -__int_as_float(0x7f800000);
            for (int i = lane; i < c; i += 32) {
                float x = cand[i];
                if (x < bound) m = fmaxf(m, x);
            }
            #pragma unroll
            for (int o = 16; o; o >>= 1) m = fmaxf(m, __shfl_xor_sync(FULLMASK, m, o));
            int cnt = 0;
            for (int i = lane; i < c; i += 32) cnt += (cand[i] == m);
            #pragma unroll
            for (int o = 16; o; o >>= 1) cnt += __shfl_xor_sync(FULLMASK, cnt, o);
            if (cnt >= remaining) { vk = m; break; }
            remaining -= cnt;
            bound = m;
        }
        if (lane == 0) s_vk = vk;
    }
    __syncthreads();                                          // B6

    // ---- 6. Masked exp + sum (offset by vk; softmax is shift-invariant) ----
    const float vk = s_vk;
    float sum = 0.0f;
    #pragma unroll
    for (int i = 0; i < VPT; i++) {
        float ev = (v[i] >= vk) ? __expf(v[i] - vk) : 0.0f;
        v[i] = ev;
        sum += ev;
    }
    #pragma unroll
    for (int o = 16; o; o >>= 1) sum += __shfl_xor_sync(FULLMASK, sum, o);
    if (lane == 0) atomicAdd(&s_sum, sum);
    __syncthreads();                                          // B7

    const float inv = __fdividef(1.0f, s_sum);

    // ---- 7. Store (coalesced float4) ----
    float4 o1 = make_float4(v[0] * inv, v[1] * inv, v[2] * inv, v[3] * inv);
    float4 o2 = make_float4(v[4] * inv, v[5] * inv, v[6] * inv, v[7] * inv);
    op4[tid]            = o1;
    op4[tid + NTHREADS] = o2;
}

extern "C" void kernel_launch(void* const* d_in, const int* in_sizes, int n_in,
                              void* d_out, int out_size) {
    const float* in  = (const float*)d_in[0];
    float*       out = (float*)d_out;
    const int nrows = in_sizes[0] / ROW_LEN;   // 2*16*2048 = 65536
    topk_softmax_kernel<<<nrows, NTHREADS>>>(in, out);
}

// round 13
// speedup vs baseline: 1.2000x; 1.0534x over previous
#include <cuda_runtime.h>
#include <cstdint>

#define ROW_LEN 2048
#define NTHREADS 256
#define NWARP 8
#define K_TOP 64
#define NBINS 512            // bins 1..511 cover x in [1.0, 5.0); bin 0 = derived catch-all
#define FSCALE 128.0f
#define FBIAS  -127.0f
#define FULLMASK 0xffffffffu

typedef unsigned long long u64;

// ---- packed f32x2 helpers (sm_103a; ptxas never auto-fuses these) ----
__device__ __forceinline__ u64 pack2(float lo, float hi) {
    u64 r;
    asm("mov.b64 %0, {%1, %2};" : "=l"(r) : "f"(lo), "f"(hi));
    return r;
}
__device__ __forceinline__ float2 unpack2(u64 p) {
    float2 r;
    asm("mov.b64 {%0, %1}, %2;" : "=f"(r.x), "=f"(r.y) : "l"(p));
    return r;
}
__device__ __forceinline__ u64 fma2(u64 a, u64 b, u64 c) {
    u64 d;
    asm("fma.rn.f32x2 %0, %1, %2, %3;" : "=l"(d) : "l"(a), "l"(b), "l"(c));
    return d;
}
__device__ __forceinline__ u64 mul2(u64 a, u64 b) {
    u64 d;
    asm("mul.rn.f32x2 %0, %1, %2;" : "=l"(d) : "l"(a), "l"(b));
    return d;
}
__device__ __forceinline__ float ex2a(float x) {
    float r;
    asm("ex2.approx.f32 %0, %1;" : "=f"(r) : "f"(x));
    return r;
}

__global__ __launch_bounds__(NTHREADS, 8)   // cap regs at 32 -> 8 CTAs/SM
void topk_softmax_kernel(const float* __restrict__ in, float* __restrict__ out) {
    const int tid  = threadIdx.x;
    const int lane = tid & 31;
    const int wid  = tid >> 5;
    const size_t rbase = (size_t)blockIdx.x * ROW_LEN;

    const float4* rp4 = reinterpret_cast<const float4*>(in + rbase);
    float4*       op4 = reinterpret_cast<float4*>(out + rbase);

    __shared__ int   hist[NBINS];
    __shared__ float cand[ROW_LEN];      // crossing-bin candidates (worst-case safe)
    __shared__ int   s_wsum[NWARP];
    __shared__ int   s_bin, s_kc, s_cnt;
    __shared__ float s_vk, s_sum;

    // ---- 1. Issue loads; zero histogram while they're in flight ----
    float4 a = rp4[tid];
    float4 b = rp4[tid + NTHREADS];
    reinterpret_cast<int2*>(hist)[tid] = make_int2(0, 0);
    if (tid == 0) { s_cnt = 0; s_sum = 0.0f; }

    float2 v2[4];
    v2[0] = make_float2(a.x, a.y); v2[1] = make_float2(a.z, a.w);
    v2[2] = make_float2(b.x, b.y); v2[3] = make_float2(b.z, b.w);
    __syncthreads();                                          // B1

    // ---- 2. Conditional tail histogram (packed binning FMAs) ----
    {
        const u64 SC = pack2(FSCALE, FSCALE);
        const u64 BI = pack2(FBIAS, FBIAS);
        #pragma unroll
        for (int j = 0; j < 4; j++) {
            float2 f = unpack2(fma2(pack2(v2[j].x, v2[j].y), SC, BI));
            if (f.x >= 1.0f) atomicAdd(&hist[min((int)f.x, NBINS - 1)], 1);
            if (f.y >= 1.0f) atomicAdd(&hist[min((int)f.y, NBINS - 1)], 1);
        }
    }
    __syncthreads();                                          // B2

    // ---- 3. Distributed suffix scan; thread t owns bins (2t, 2t+1) ----
    const int2 h = reinterpret_cast<int2*>(hist)[tid];
    const int lsum = h.x + h.y;
    int s = lsum;                                 // warp suffix incl. self
    #pragma unroll
    for (int o = 1; o < 32; o <<= 1) {
        int t = __shfl_down_sync(FULLMASK, s, o);
        if (lane + o < 32) s += t;
    }
    if (lane == 0) s_wsum[wid] = s;
    __syncthreads();                                          // B3

    int T = s - lsum;                             // count in bins strictly above my pair
    #pragma unroll
    for (int w = 1; w < NWARP; w++)
        if (w > wid) T += s_wsum[w];

    if (T < K_TOP && T + lsum >= K_TOP) {         // unique thread owns the crossing
        const int nsuf = T + h.y;                 // bin 2t+1 is the higher bin
        if (nsuf >= K_TOP) {
            s_bin = tid * 2 + 1;
            s_kc  = K_TOP - T;
        } else {
            s_bin = tid * 2;
            s_kc  = K_TOP - nsuf;
        }
    }
    if (tid == 0) {                               // catch-all: threshold below range
        const int total = T + lsum;               // thread 0's suffix = all histed elems
        if (total < K_TOP) {
            s_bin = 0;
            s_kc  = K_TOP - total;
        }
    }
    __syncthreads();                                          // B4

    // ---- 4. Compact the crossing bin's elements (same packed FMA as binning) ----
    const int bstar = s_bin;
    const int kc    = s_kc;
    const float flo = (bstar == 0)         ? -__int_as_float(0x7f800000) : (float)bstar;
    const float fhi = (bstar == NBINS - 1) ?  __int_as_float(0x7f800000) : (float)(bstar + 1);
    {
        const u64 SC = pack2(FSCALE, FSCALE);
        const u64 BI = pack2(FBIAS, FBIAS);
        #pragma unroll
        for (int j = 0; j < 4; j++) {
            float2 f = unpack2(fma2(pack2(v2[j].x, v2[j].y), SC, BI));
            if (f.x >= flo && f.x < fhi) { int i0 = atomicAdd(&s_cnt, 1); cand[i0] = v2[j].x; }
            if (f.y >= flo && f.y < fhi) { int i1 = atomicAdd(&s_cnt, 1); cand[i1] = v2[j].y; }
        }
    }
    __syncthreads();                                          // B5

    // ---- 5. Warp 0 only: exact kc-th largest among candidates (tie-robust) ----
    if (wid == 0) {
        const int c = s_cnt;                      // usually ~1-2
        int   remaining = kc;
        float bound = __int_as_float(0x7f800000); // +inf
        float vk;
        for (;;) {
            float m = -__int_as_float(0x7f800000);
            for (int i = lane; i < c; i += 32) {
                float x = cand[i];
                if (x < bound) m = fmaxf(m, x);
            }
            #pragma unroll
            for (int o = 16; o; o >>= 1) m = fmaxf(m, __shfl_xor_sync(FULLMASK, m, o));
            int cnt = 0;
            for (int i = lane; i < c; i += 32) cnt += (cand[i] == m);
            #pragma unroll
            for (int o = 16; o; o >>= 1) cnt += __shfl_xor_sync(FULLMASK, cnt, o);
            if (cnt >= remaining) { vk = m; break; }
            remaining -= cnt;
            bound = m;
        }
        if (lane == 0) s_vk = vk;
    }
    __syncthreads();                                          // B6

    // ---- 6. Masked exp + sum: e = ex2(fma(v, log2e, -vk*log2e)), mask on v>=vk ----
    const float vk = s_vk;
    float sum;
    {
        const float L2E = 1.4426950408889634f;
        const u64 L2 = pack2(L2E, L2E);
        const float nc = -vk * L2E;
        const u64 NC = pack2(nc, nc);
        sum = 0.0f;
        #pragma unroll
        for (int j = 0; j < 4; j++) {
            float2 t = unpack2(fma2(pack2(v2[j].x, v2[j].y), L2, NC));
            float e0 = ex2a(t.x);
            float e1 = ex2a(t.y);
            e0 = (v2[j].x >= vk) ? e0 : 0.0f;
            e1 = (v2[j].y >= vk) ? e1 : 0.0f;
            v2[j].x = e0; v2[j].y = e1;
            sum += e0 + e1;
        }
    }
    #pragma unroll
    for (int o = 16; o; o >>= 1) sum += __shfl_xor_sync(FULLMASK, sum, o);
    if (lane == 0) atomicAdd(&s_sum, sum);
    __syncthreads();                                          // B7

    const float inv = __fdividef(1.0f, s_sum);

    // ---- 7. Scale (packed) + store (coalesced float4) ----
    const u64 IV = pack2(inv, inv);
    float2 o0 = unpack2(mul2(pack2(v2[0].x, v2[0].y), IV));
    float2 o1 = unpack2(mul2(pack2(v2[1].x, v2[1].y), IV));
    float2 o2 = unpack2(mul2(pack2(v2[2].x, v2[2].y), IV));
    float2 o3 = unpack2(mul2(pack2(v2[3].x, v2[3].y), IV));
    op4[tid]            = make_float4(o0.x, o0.y, o1.x, o1.y);
    op4[tid + NTHREADS] = make_float4(o2.x, o2.y, o3.x, o3.y);
}

extern "C" void kernel_launch(void* const* d_in, const int* in_sizes, int n_in,
                              void* d_out, int out_size) {
    const float* in  = (const float*)d_in[0];
    float*       out = (float*)d_out;
    const int nrows = in_sizes[0] / ROW_LEN;   // 2*16*2048 = 65536
    topk_softmax_kernel<<<nrows, NTHREADS>>>(in, out);
}

// round 14
// speedup vs baseline: 1.3771x; 1.1476x over previous
#include <cuda_runtime.h>
#include <cstdint>

#define ROW_LEN 2048
#define NTHREADS 256
#define NWARP 8
#define K_TOP 64
#define NBINS 512            // bins 1..511 cover x in [1.0, 5.0); bin 0 = derived catch-all
#define FSCALE 128.0f
#define FBIAS  -127.0f
#define FULLMASK 0xffffffffu

typedef unsigned long long u64;

// ---- packed f32x2 helpers (sm_103a) ----
__device__ __forceinline__ u64 pack2(float lo, float hi) {
    u64 r;
    asm("mov.b64 %0, {%1, %2};" : "=l"(r) : "f"(lo), "f"(hi));
    return r;
}
__device__ __forceinline__ float2 unpack2(u64 p) {
    float2 r;
    asm("mov.b64 {%0, %1}, %2;" : "=f"(r.x), "=f"(r.y) : "l"(p));
    return r;
}
__device__ __forceinline__ u64 fma2(u64 a, u64 b, u64 c) {
    u64 d;
    asm("fma.rn.f32x2 %0, %1, %2, %3;" : "=l"(d) : "l"(a), "l"(b), "l"(c));
    return d;
}
__device__ __forceinline__ u64 mul2(u64 a, u64 b) {
    u64 d;
    asm("mul.rn.f32x2 %0, %1, %2;" : "=l"(d) : "l"(a), "l"(b));
    return d;
}
__device__ __forceinline__ float ex2a(float x) {
    float r;
    asm("ex2.approx.f32 %0, %1;" : "=f"(r) : "f"(x));
    return r;
}

__global__ __launch_bounds__(NTHREADS, 8)   // cap regs at 32 -> 8 CTAs/SM
void topk_softmax_kernel(const float* __restrict__ in, float* __restrict__ out) {
    const int tid  = threadIdx.x;
    const int lane = tid & 31;
    const int wid  = tid >> 5;
    const size_t rbase = (size_t)blockIdx.x * ROW_LEN;

    const float4* rp4 = reinterpret_cast<const float4*>(in + rbase);
    float4*       op4 = reinterpret_cast<float4*>(out + rbase);

    __shared__ int   hist[NBINS];
    __shared__ float cand[ROW_LEN];      // fallback-only candidate buffer
    __shared__ int   s_wsum[NWARP];
    __shared__ int   s_bin, s_kc, s_cnt, s_mode, s_vkbits;
    __shared__ float s_vk, s_sum;

    // ---- 1. Issue loads; zero histogram while they're in flight ----
    float4 a = rp4[tid];
    float4 b = rp4[tid + NTHREADS];
    reinterpret_cast<int2*>(hist)[tid] = make_int2(0, 0);
    if (tid == 0) { s_cnt = 0; s_sum = 0.0f; }

    float2 v2[4];
    v2[0] = make_float2(a.x, a.y); v2[1] = make_float2(a.z, a.w);
    v2[2] = make_float2(b.x, b.y); v2[3] = make_float2(b.z, b.w);
    __syncthreads();                                          // B1

    // ---- 2. Conditional tail histogram (packed binning FMAs) ----
    {
        const u64 SC = pack2(FSCALE, FSCALE);
        const u64 BI = pack2(FBIAS, FBIAS);
        #pragma unroll
        for (int j = 0; j < 4; j++) {
            float2 f = unpack2(fma2(pack2(v2[j].x, v2[j].y), SC, BI));
            if (f.x >= 1.0f) atomicAdd(&hist[min((int)f.x, NBINS - 1)], 1);
            if (f.y >= 1.0f) atomicAdd(&hist[min((int)f.y, NBINS - 1)], 1);
        }
    }
    __syncthreads();                                          // B2

    // ---- 3. Distributed suffix scan; thread t owns bins (2t, 2t+1) ----
    const int2 h = reinterpret_cast<int2*>(hist)[tid];
    const int lsum = h.x + h.y;
    int s = lsum;                                 // warp suffix incl. self
    #pragma unroll
    for (int o = 1; o < 32; o <<= 1) {
        int t = __shfl_down_sync(FULLMASK, s, o);
        if (lane + o < 32) s += t;
    }
    if (lane == 0) s_wsum[wid] = s;
    __syncthreads();                                          // B3

    int T = s - lsum;                             // count in bins strictly above my pair
    #pragma unroll
    for (int w = 1; w < NWARP; w++)
        if (w > wid) T += s_wsum[w];

    if (T < K_TOP && T + lsum >= K_TOP) {         // unique thread owns the crossing
        int bin, kc, hcnt;
        const int nsuf = T + h.y;                 // bin 2t+1 is the higher bin
        if (nsuf >= K_TOP) { bin = tid * 2 + 1; kc = K_TOP - T;    hcnt = h.y; }
        else               { bin = tid * 2;     kc = K_TOP - nsuf; hcnt = h.x; }
        s_bin = bin;
        s_kc  = kc;
        if (kc == 1)         { s_mode = 1; s_vkbits = 0; }          // take bin max
        else if (kc == hcnt) { s_mode = 2; s_vkbits = 0x7f800000; } // take bin min
        else                 { s_mode = 0; }                        // rare fallback
    }
    if (tid == 0) {                               // catch-all: threshold below range
        const int total = T + lsum;               // thread 0's suffix = all histed elems
        if (total < K_TOP) {
            s_bin  = 0;
            s_kc   = K_TOP - total;
            s_mode = 0;
        }
    }
    __syncthreads();                                          // B4

    // ---- 4. Resolve vk ----
    const int bstar = s_bin;
    const int mode  = s_mode;
    const float flo = (bstar == 0)         ? -__int_as_float(0x7f800000) : (float)bstar;
    const float fhi = (bstar == NBINS - 1) ?  __int_as_float(0x7f800000) : (float)(bstar + 1);
    {
        const u64 SC = pack2(FSCALE, FSCALE);
        const u64 BI = pack2(FBIAS, FBIAS);
        if (mode == 1) {          // vk = max of bin members (positive floats: int bits monotone)
            #pragma unroll
            for (int j = 0; j < 4; j++) {
                float2 f = unpack2(fma2(pack2(v2[j].x, v2[j].y), SC, BI));
                if (f.x >= flo && f.x < fhi) atomicMax(&s_vkbits, __float_as_int(v2[j].x));
                if (f.y >= flo && f.y < fhi) atomicMax(&s_vkbits, __float_as_int(v2[j].y));
            }
        } else if (mode == 2) {   // vk = min of bin members
            #pragma unroll
            for (int j = 0; j < 4; j++) {
                float2 f = unpack2(fma2(pack2(v2[j].x, v2[j].y), SC, BI));
                if (f.x >= flo && f.x < fhi) atomicMin(&s_vkbits, __float_as_int(v2[j].x));
                if (f.y >= flo && f.y < fhi) atomicMin(&s_vkbits, __float_as_int(v2[j].y));
            }
        } else {                  // fallback: compact candidates
            #pragma unroll
            for (int j = 0; j < 4; j++) {
                float2 f = unpack2(fma2(pack2(v2[j].x, v2[j].y), SC, BI));
                if (f.x >= flo && f.x < fhi) { int i0 = atomicAdd(&s_cnt, 1); cand[i0] = v2[j].x; }
                if (f.y >= flo && f.y < fhi) { int i1 = atomicAdd(&s_cnt, 1); cand[i1] = v2[j].y; }
            }
        }
    }
    __syncthreads();                                          // B5

    if (mode == 0) {              // rare exact select (block-uniform branch)
        if (wid == 0) {
            const int c  = s_cnt;
            const int kc = s_kc;
            int   remaining = kc;
            float bound = __int_as_float(0x7f800000);
            float vk;
            for (;;) {
                float m = -__int_as_float(0x7f800000);
                for (int i = lane; i < c; i += 32) {
                    float x = cand[i];
                    if (x < bound) m = fmaxf(m, x);
                }
                #pragma unroll
                for (int o = 16; o; o >>= 1) m = fmaxf(m, __shfl_xor_sync(FULLMASK, m, o));
                int cnt = 0;
                for (int i = lane; i < c; i += 32) cnt += (cand[i] == m);
                #pragma unroll
                for (int o = 16; o; o >>= 1) cnt += __shfl_xor_sync(FULLMASK, cnt, o);
                if (cnt >= remaining) { vk = m; break; }
                remaining -= cnt;
                bound = m;
            }
            if (lane == 0) s_vk = vk;
        }
        __syncthreads();                                      // B6 (rare)
    }

    const float vk = (mode != 0) ? __int_as_float(s_vkbits) : s_vk;

    // ---- 5. Masked exp + sum: e = ex2(fma(v, log2e, -vk*log2e)), mask on v>=vk ----
    float sum;
    {
        const float L2E = 1.4426950408889634f;
        const u64 L2 = pack2(L2E, L2E);
        const float nc = -vk * L2E;
        const u64 NC = pack2(nc, nc);
        sum = 0.0f;
        #pragma unroll
        for (int j = 0; j < 4; j++) {
            float2 t = unpack2(fma2(pack2(v2[j].x, v2[j].y), L2, NC));
            float e0 = ex2a(t.x);
            float e1 = ex2a(t.y);
            e0 = (v2[j].x >= vk) ? e0 : 0.0f;
            e1 = (v2[j].y >= vk) ? e1 : 0.0f;
            v2[j].x = e0; v2[j].y = e1;
            sum += e0 + e1;
        }
    }
    #pragma unroll
    for (int o = 16; o; o >>= 1) sum += __shfl_xor_sync(FULLMASK, sum, o);
    if (lane == 0) atomicAdd(&s_sum, sum);
    __syncthreads();                                          // B6/B7

    const float inv = __fdividef(1.0f, s_sum);

    // ---- 6. Scale (packed) + store (coalesced float4) ----
    const u64 IV = pack2(inv, inv);
    float2 o0 = unpack2(mul2(pack2(v2[0].x, v2[0].y), IV));
    float2 o1 = unpack2(mul2(pack2(v2[1].x, v2[1].y), IV));
    float2 o2 = unpack2(mul2(pack2(v2[2].x, v2[2].y), IV));
    float2 o3 = unpack2(mul2(pack2(v2[3].x, v2[3].y), IV));
    op4[tid]            = make_float4(o0.x, o0.y, o1.x, o1.y);
    op4[tid + NTHREADS] = make_float4(o2.x, o2.y, o3.x, o3.y);
}

extern "C" void kernel_launch(void* const* d_in, const int* in_sizes, int n_in,
                              void* d_out, int out_size) {
    const float* in  = (const float*)d_in[0];
    float*       out = (float*)d_out;
    const int nrows = in_sizes[0] / ROW_LEN;   // 2*16*2048 = 65536
    topk_softmax_kernel<<<nrows, NTHREADS>>>(in, out);
}